// round 14
// baseline (speedup 1.0000x reference)
#include <cuda_runtime.h>

#define HEADS 4
#define DIM   64
#define BB    8
#define QQ    128
#define VV    128
#define NN    (BB*QQ)   // 1024

typedef unsigned long long ull;

// Scratch (device globals — no allocation allowed). g_VU has one row of pad
// so the recurrence can prefetch one step past the end unconditionally.
__device__ float2 g_QU[HEADS * NN * DIM];                 // [h][n][j] complex
__device__ float2 g_VU[HEADS * BB * VV * DIM + DIM];      // [h][b][v][j] complex (+pad)
__device__ float  g_acc[NN * HEADS * DIM];                // [n][h*64+j] real

__device__ __forceinline__ float rsqrt_apx(float s) {
    float r; asm("rsqrt.approx.f32 %0,%1;" : "=f"(r) : "f"(s)); return r;
}
// f32x2 helpers (layer-1 only; real coefficients, no swaps)
__device__ __forceinline__ ull pk(float lo, float hi) {
    ull d; asm("mov.b64 %0,{%1,%2};" : "=l"(d) : "f"(lo), "f"(hi)); return d;
}
__device__ __forceinline__ float lo32(ull a) {
    float x; asm("{ .reg .b32 t; mov.b64 {%0,t},%1; }" : "=f"(x) : "l"(a)); return x;
}
__device__ __forceinline__ float hi32(ull a) {
    float x; asm("{ .reg .b32 t; mov.b64 {t,%0},%1; }" : "=f"(x) : "l"(a)); return x;
}
__device__ __forceinline__ ull fma2(ull a, ull b, ull c) {
    ull d; asm("fma.rn.f32x2 %0,%1,%2,%3;" : "=l"(d) : "l"(a), "l"(b), "l"(c)); return d;
}
__device__ __forceinline__ ull mul2(ull a, ull b) {
    ull d; asm("mul.rn.f32x2 %0,%1,%2;" : "=l"(d) : "l"(a), "l"(b)); return d;
}

// ---------------------------------------------------------------------------
// Kernel 1 (tiled GEMM): for part p (0:queries->g_QU, 1:values->g_VU), head h,
// 64-row tile:  out[row, j] = sum_k x[row,k] * U[h, p*64+k, j]  (complex)
// grid = 128 blocks (1/SM), 512 threads. k-loop blocked by 4 so x is read as
// one warp-broadcast LDS.128 per row per k4-block: 12 LDS per 64 FMA (was 24).
// Thread t: j = 2*(t&31), 2*(t&31)+1; rows (t>>5)*4 .. +3.
// ---------------------------------------------------------------------------
__global__ void __launch_bounds__(512) k_compute_u(
    const float* __restrict__ q,      // [1024,64]
    const float* __restrict__ vals,   // [1024,64]
    const float* __restrict__ Ure,    // [4,128,64]
    const float* __restrict__ Uim)
{
    __shared__ float x_s[64 * 64];    // [r][k]
    __shared__ float ur_s[64 * 64];   // [k][j]
    __shared__ float ui_s[64 * 64];

    int t    = threadIdx.x;
    int tile = blockIdx.x & 15;
    int p    = (blockIdx.x >> 4) & 1;
    int h    = blockIdx.x >> 5;

    // stage x tile (64 rows x 64 cols) = 1024 float4, conflict-free
    const float4* src4 = (const float4*)((p == 0 ? q : vals) + tile * 64 * 64);
    float4* xs4 = (float4*)x_s;
    #pragma unroll
    for (int i = 0; i < 2; i++) xs4[t + 512 * i] = __ldg(src4 + t + 512 * i);

    // stage U tiles (64 k x 64 j, re and im) = 1024 float4 each
    const float4* ur4 = (const float4*)(Ure + h * 8192 + p * 4096);
    const float4* ui4 = (const float4*)(Uim + h * 8192 + p * 4096);
    float4* urs4 = (float4*)ur_s;
    float4* uis4 = (float4*)ui_s;
    #pragma unroll
    for (int i = 0; i < 2; i++) {
        urs4[t + 512 * i] = __ldg(ur4 + t + 512 * i);
        uis4[t + 512 * i] = __ldg(ui4 + t + 512 * i);
    }
    __syncthreads();

    int j0 = 2 * (t & 31);            // complex columns j0, j0+1
    int rg = t >> 5;                  // 0..15 -> rows rg*4 .. rg*4+3

    float a0r[4], a0i[4], a1r[4], a1i[4];
    #pragma unroll
    for (int i = 0; i < 4; i++) { a0r[i] = a0i[i] = a1r[i] = a1i[i] = 0.f; }

    #pragma unroll 4
    for (int k4 = 0; k4 < 64; k4 += 4) {
        // one LDS.128 per row (warp-uniform broadcast), 4 k's at a time
        float4 x0 = *(const float4*)&x_s[(rg * 4 + 0) * 64 + k4];
        float4 x1 = *(const float4*)&x_s[(rg * 4 + 1) * 64 + k4];
        float4 x2 = *(const float4*)&x_s[(rg * 4 + 2) * 64 + k4];
        float4 x3 = *(const float4*)&x_s[(rg * 4 + 3) * 64 + k4];
        const float* xp0 = (const float*)&x0;
        const float* xp1 = (const float*)&x1;
        const float* xp2 = (const float*)&x2;
        const float* xp3 = (const float*)&x3;
        #pragma unroll
        for (int kk = 0; kk < 4; kk++) {
            float2 ur = *(const float2*)&ur_s[(k4 + kk) * 64 + j0];
            float2 ui = *(const float2*)&ui_s[(k4 + kk) * 64 + j0];
            float xv0 = xp0[kk], xv1 = xp1[kk], xv2 = xp2[kk], xv3 = xp3[kk];
            a0r[0] = fmaf(xv0, ur.x, a0r[0]);  a0i[0] = fmaf(xv0, ui.x, a0i[0]);
            a1r[0] = fmaf(xv0, ur.y, a1r[0]);  a1i[0] = fmaf(xv0, ui.y, a1i[0]);
            a0r[1] = fmaf(xv1, ur.x, a0r[1]);  a0i[1] = fmaf(xv1, ui.x, a0i[1]);
            a1r[1] = fmaf(xv1, ur.y, a1r[1]);  a1i[1] = fmaf(xv1, ui.y, a1i[1]);
            a0r[2] = fmaf(xv2, ur.x, a0r[2]);  a0i[2] = fmaf(xv2, ui.x, a0i[2]);
            a1r[2] = fmaf(xv2, ur.y, a1r[2]);  a1i[2] = fmaf(xv2, ui.y, a1i[2]);
            a0r[3] = fmaf(xv3, ur.x, a0r[3]);  a0i[3] = fmaf(xv3, ui.x, a0i[3]);
            a1r[3] = fmaf(xv3, ur.y, a1r[3]);  a1i[3] = fmaf(xv3, ui.y, a1i[3]);
        }
    }

    float2* dst = (p == 0 ? g_QU : g_VU) + (size_t)h * NN * DIM + (size_t)tile * 64 * DIM;
    #pragma unroll
    for (int i = 0; i < 4; i++) {
        int row = rg * 4 + i;
        *(float4*)&dst[row * DIM + j0] = make_float4(a0r[i], a0i[i], a1r[i], a1i[i]);
    }
}

// ---------------------------------------------------------------------------
// Kernel 2: EUNN+modrelu recurrence — FROZEN R12 body (best measured).
// One warp per (h, n). Lane l owns complex elems 2l (A) and 2l+1 (B), state
// packed (re,im) for layer-1 only; everything downstream scalar.
//   tA = c1*A - s1*B ; nB = s1*A + c1*B          (packed f32x2, real coeffs)
//   zB = P*nB - Q*xd + in,   P = E*c2,  Q = E*s2*e1_{l+1},  E = e^{i(wB+phi2_l)}
//   zA = G'*tA + F*xu + in,  G' = e^{i wA}*c2p*e1,  F = e^{i wA}*s2p
//   xd = tA of lane l+1, xu = nB of lane l-1
//   modrelu: r = rsqrt(max(|z|^2,1e-10)) ~= 1/(|z|+1e-5);
//            sc = max(1 + (b-1e-5)*r, 0);  h = z*sc
// ---------------------------------------------------------------------------
__global__ void __launch_bounds__(128) k_recur(
    const float* __restrict__ bias,   // [4,64]
    const float* __restrict__ th1,    // [4,32]
    const float* __restrict__ ph1,    // [4,32]
    const float* __restrict__ th2,    // [4,31]
    const float* __restrict__ ph2,    // [4,31]
    const float* __restrict__ om)     // [4,64]
{
    const unsigned FULL = 0xffffffffu;
    int w = (blockIdx.x * blockDim.x + threadIdx.x) >> 5;   // 0..4095
    int l = threadIdx.x & 31;
    int h = w >> 10;
    int n = w & (NN - 1);
    int b = n >> 7;

    // layer-1 constants
    float c1, s1, e1r, e1i;
    sincosf(th1[h * 32 + l], &s1, &c1);
    sincosf(ph1[h * 32 + l], &e1i, &e1r);

    // layer-2 constants (pair l couples elems 2l+1, 2l+2)
    float c2 = 1.f, s2 = 0.f, p2 = 0.f;
    if (l < 31) {
        sincosf(th2[h * 31 + l], &s2, &c2);
        p2 = ph2[h * 31 + l];
    }
    float c2p = 1.f, s2p = 0.f;
    if (l > 0) sincosf(th2[h * 31 + l - 1], &s2p, &c2p);

    float omA = om[h * 64 + 2 * l];
    float omB = om[h * 64 + 2 * l + 1];

    // e1 of lane l+1 (lane 31: unused, s2=0 kills it)
    float e1nr = __shfl_down_sync(FULL, e1r, 1);
    float e1ni = __shfl_down_sync(FULL, e1i, 1);

    // E = e^{i(omB + phi2_l)}; P = E*c2; Q = E*s2*e1_next
    float Er, Ei;
    sincosf(omB + p2, &Ei, &Er);
    float Pr = c2 * Er, Pi = c2 * Ei;
    float Qr = s2 * (Er * e1nr - Ei * e1ni);
    float Qi = s2 * (Er * e1ni + Ei * e1nr);
    // G' = e^{i omA}*c2p*e1 ; F = e^{i omA}*s2p
    float cA_, sA_;
    sincosf(omA, &sA_, &cA_);
    float Gr = c2p * (cA_ * e1r - sA_ * e1i);
    float Gi = c2p * (cA_ * e1i + sA_ * e1r);
    float Fr = s2p * cA_, Fi = s2p * sA_;

    float bAp = bias[h * 64 + 2 * l]     - 1e-5f;
    float bBp = bias[h * 64 + 2 * l + 1] - 1e-5f;

    // packed real-coefficient constants for layer 1
    ull c1p  = pk(c1, c1);
    ull s1p  = pk(s1, s1);
    ull ns1p = pk(-s1, -s1);

    // per-warp constant input (QU, scalar) and per-step VU stream
    float4 qu = __ldg((const float4*)&g_QU[(h * NN + n) * DIM + 2 * l]);
    const float4* vup = (const float4*)&g_VU[((h * BB + b) * VV) * DIM + 2 * l];

    ull A2 = 0ull, B2 = 0ull;   // (re, im) packed state

    float4 vu = __ldg(vup); vup += DIM / 2;   // prefetch step 0

    #pragma unroll 4
    for (int v = 0; v < VV; v++) {
        float4 vun = __ldg(vup); vup += DIM / 2;   // prefetch next (pad covers v=127)

        // input term — scalar adds
        float inAr = qu.x + vu.x, inAi = qu.y + vu.y;
        float inBr = qu.z + vu.z, inBi = qu.w + vu.w;

        // layer 1 (packed, real coefficients)
        ull tA2 = fma2(c1p, A2, mul2(ns1p, B2));   // c1*A - s1*B  (re,im)
        ull nB2 = fma2(s1p, A2, mul2(c1p, B2));    // s1*A + c1*B  (re,im)

        // extract once, then shuffle scalars
        float tAr = lo32(tA2), tAi = hi32(tA2);
        float nBr = lo32(nB2), nBi = hi32(nB2);

        float xur = __shfl_up_sync(FULL, nBr, 1);     // nB of lane l-1
        float xui = __shfl_up_sync(FULL, nBi, 1);
        float xdr = __shfl_down_sync(FULL, tAr, 1);   // tA of lane l+1
        float xdi = __shfl_down_sync(FULL, tAi, 1);

        // B path: zB = P*nB - Q*xd + in   (complex, folded)
        float zBr = fmaf(Pr, nBr, fmaf(-Pi, nBi, fmaf(-Qr, xdr, fmaf( Qi, xdi, inBr))));
        float zBi = fmaf(Pr, nBi, fmaf( Pi, nBr, fmaf(-Qr, xdi, fmaf(-Qi, xdr, inBi))));

        // A path: zA = G'*tA + F*xu + in  (complex, folded)
        float zAr = fmaf(Gr, tAr, fmaf(-Gi, tAi, fmaf(Fr, xur, fmaf(-Fi, xui, inAr))));
        float zAi = fmaf(Gr, tAi, fmaf( Gi, tAr, fmaf(Fr, xui, fmaf( Fi, xur, inAi))));

        // modrelu — single MUFU per element; guard on the ALU pipe
        float sA = fmaf(zAi, zAi, zAr * zAr);
        float sB = fmaf(zBi, zBi, zBr * zBr);
        float rA = rsqrt_apx(fmaxf(sA, 1e-10f));
        float rB = rsqrt_apx(fmaxf(sB, 1e-10f));
        float scA = fmaxf(fmaf(bAp, rA, 1.0f), 0.0f);
        float scB = fmaxf(fmaf(bBp, rB, 1.0f), 0.0f);
        A2 = pk(zAr * scA, zAi * scA);
        B2 = pk(zBr * scB, zBi * scB);

        vu = vun;
    }

    float2* accp = (float2*)&g_acc[n * (HEADS * DIM) + h * DIM + 2 * l];
    *accp = make_float2(lo32(A2), lo32(B2));
}

// ---------------------------------------------------------------------------
// Kernel 3: y = acc @ W + b   ([1024,256] @ [256,64])
// ---------------------------------------------------------------------------
#define AST 264
__global__ void __launch_bounds__(256) k_proj(
    const float* __restrict__ W,    // [256,64]
    const float* __restrict__ bd,   // [64]
    float* __restrict__ out)        // [1024,64]
{
    __shared__ float a_s[16 * AST];
    int t = threadIdx.x;
    int row0 = blockIdx.x * 16;

    const float4* g4 = (const float4*)(g_acc + row0 * 256);
    #pragma unroll
    for (int i = 0; i < 4; i++) {
        int g = t + 256 * i;
        int r = g >> 6, c4 = g & 63;
        *(float4*)&a_s[r * AST + c4 * 4] = __ldg(g4 + g);
    }
    __syncthreads();

    int tx = t & 15, ty = t >> 4;
    float4 s = __ldg((const float4*)(bd + 4 * tx));
    const float* arow = a_s + ty * AST;

    #pragma unroll 4
    for (int k = 0; k < 256; k++) {
        float a = arow[k];
        float4 wv = __ldg((const float4*)(W + k * 64 + 4 * tx));
        s.x = fmaf(a, wv.x, s.x);
        s.y = fmaf(a, wv.y, s.y);
        s.z = fmaf(a, wv.z, s.z);
        s.w = fmaf(a, wv.w, s.w);
    }
    *(float4*)(out + (row0 + ty) * 64 + 4 * tx) = s;
}

// ---------------------------------------------------------------------------
extern "C" void kernel_launch(void* const* d_in, const int* in_sizes, int n_in,
                              void* d_out, int out_size)
{
    const float* queries = (const float*)d_in[0];
    const float* values  = (const float*)d_in[1];
    const float* U_re    = (const float*)d_in[2];
    const float* U_im    = (const float*)d_in[3];
    const float* bias    = (const float*)d_in[4];
    const float* theta1  = (const float*)d_in[5];
    const float* phi1    = (const float*)d_in[6];
    const float* theta2  = (const float*)d_in[7];
    const float* phi2    = (const float*)d_in[8];
    const float* omega   = (const float*)d_in[9];
    const float* W_dense = (const float*)d_in[10];
    const float* b_dense = (const float*)d_in[11];
    float* out = (float*)d_out;

    k_compute_u<<<128, 512>>>(queries, values, U_re, U_im);
    k_recur<<<1024, 128>>>(bias, theta1, phi1, theta2, phi2, omega);
    k_proj<<<64, 256>>>(W_dense, b_dense, out);
}

// round 15
// speedup vs baseline: 1.5310x; 1.5310x over previous
#include <cuda_runtime.h>

#define HEADS 4
#define DIM   64
#define BB    8
#define QQ    128
#define VV    128
#define NN    (BB*QQ)   // 1024

typedef unsigned long long ull;

// Scratch (device globals — no allocation allowed). g_VU has one row of pad
// so the recurrence can prefetch one step past the end unconditionally.
__device__ float2 g_QU[HEADS * NN * DIM];                 // [h][n][j] complex
__device__ float2 g_VU[HEADS * BB * VV * DIM + DIM];      // [h][b][v][j] complex (+pad)
__device__ float  g_acc[NN * HEADS * DIM];                // [n][h*64+j] real

__device__ __forceinline__ float rsqrt_apx(float s) {
    float r; asm("rsqrt.approx.f32 %0,%1;" : "=f"(r) : "f"(s)); return r;
}
// f32x2 helpers (layer-1 only; real coefficients, no swaps)
__device__ __forceinline__ ull pk(float lo, float hi) {
    ull d; asm("mov.b64 %0,{%1,%2};" : "=l"(d) : "f"(lo), "f"(hi)); return d;
}
__device__ __forceinline__ float lo32(ull a) {
    float x; asm("{ .reg .b32 t; mov.b64 {%0,t},%1; }" : "=f"(x) : "l"(a)); return x;
}
__device__ __forceinline__ float hi32(ull a) {
    float x; asm("{ .reg .b32 t; mov.b64 {t,%0},%1; }" : "=f"(x) : "l"(a)); return x;
}
__device__ __forceinline__ ull fma2(ull a, ull b, ull c) {
    ull d; asm("fma.rn.f32x2 %0,%1,%2,%3;" : "=l"(d) : "l"(a), "l"(b), "l"(c)); return d;
}
__device__ __forceinline__ ull mul2(ull a, ull b) {
    ull d; asm("mul.rn.f32x2 %0,%1,%2;" : "=l"(d) : "l"(a), "l"(b)); return d;
}

// ---------------------------------------------------------------------------
// Kernel 1 (tiled GEMM): for part p (0:queries->g_QU, 1:values->g_VU), head h,
// 64-row tile:  out[row, j] = sum_k x[row,k] * U[h, p*64+k, j]  (complex)
// grid = 128 blocks (1/SM), 512 threads. k-loop blocked by 4 so x is read as
// one warp-broadcast LDS.128 per row per k4-block: 12 LDS per 64 FMA.
// (Verified win in R14: 7.4us clock-normalized vs 8.9us for per-k scalar x.)
// ---------------------------------------------------------------------------
__global__ void __launch_bounds__(512) k_compute_u(
    const float* __restrict__ q,      // [1024,64]
    const float* __restrict__ vals,   // [1024,64]
    const float* __restrict__ Ure,    // [4,128,64]
    const float* __restrict__ Uim)
{
    __shared__ float x_s[64 * 64];    // [r][k]
    __shared__ float ur_s[64 * 64];   // [k][j]
    __shared__ float ui_s[64 * 64];

    int t    = threadIdx.x;
    int tile = blockIdx.x & 15;
    int p    = (blockIdx.x >> 4) & 1;
    int h    = blockIdx.x >> 5;

    // stage x tile (64 rows x 64 cols) = 1024 float4, conflict-free
    const float4* src4 = (const float4*)((p == 0 ? q : vals) + tile * 64 * 64);
    float4* xs4 = (float4*)x_s;
    #pragma unroll
    for (int i = 0; i < 2; i++) xs4[t + 512 * i] = __ldg(src4 + t + 512 * i);

    // stage U tiles (64 k x 64 j, re and im) = 1024 float4 each
    const float4* ur4 = (const float4*)(Ure + h * 8192 + p * 4096);
    const float4* ui4 = (const float4*)(Uim + h * 8192 + p * 4096);
    float4* urs4 = (float4*)ur_s;
    float4* uis4 = (float4*)ui_s;
    #pragma unroll
    for (int i = 0; i < 2; i++) {
        urs4[t + 512 * i] = __ldg(ur4 + t + 512 * i);
        uis4[t + 512 * i] = __ldg(ui4 + t + 512 * i);
    }
    __syncthreads();

    int j0 = 2 * (t & 31);            // complex columns j0, j0+1
    int rg = t >> 5;                  // 0..15 -> rows rg*4 .. rg*4+3

    float a0r[4], a0i[4], a1r[4], a1i[4];
    #pragma unroll
    for (int i = 0; i < 4; i++) { a0r[i] = a0i[i] = a1r[i] = a1i[i] = 0.f; }

    #pragma unroll 4
    for (int k4 = 0; k4 < 64; k4 += 4) {
        // one LDS.128 per row (warp-uniform broadcast), 4 k's at a time
        float4 x0 = *(const float4*)&x_s[(rg * 4 + 0) * 64 + k4];
        float4 x1 = *(const float4*)&x_s[(rg * 4 + 1) * 64 + k4];
        float4 x2 = *(const float4*)&x_s[(rg * 4 + 2) * 64 + k4];
        float4 x3 = *(const float4*)&x_s[(rg * 4 + 3) * 64 + k4];
        const float* xp0 = (const float*)&x0;
        const float* xp1 = (const float*)&x1;
        const float* xp2 = (const float*)&x2;
        const float* xp3 = (const float*)&x3;
        #pragma unroll
        for (int kk = 0; kk < 4; kk++) {
            float2 ur = *(const float2*)&ur_s[(k4 + kk) * 64 + j0];
            float2 ui = *(const float2*)&ui_s[(k4 + kk) * 64 + j0];
            float xv0 = xp0[kk], xv1 = xp1[kk], xv2 = xp2[kk], xv3 = xp3[kk];
            a0r[0] = fmaf(xv0, ur.x, a0r[0]);  a0i[0] = fmaf(xv0, ui.x, a0i[0]);
            a1r[0] = fmaf(xv0, ur.y, a1r[0]);  a1i[0] = fmaf(xv0, ui.y, a1i[0]);
            a0r[1] = fmaf(xv1, ur.x, a0r[1]);  a0i[1] = fmaf(xv1, ui.x, a0i[1]);
            a1r[1] = fmaf(xv1, ur.y, a1r[1]);  a1i[1] = fmaf(xv1, ui.y, a1i[1]);
            a0r[2] = fmaf(xv2, ur.x, a0r[2]);  a0i[2] = fmaf(xv2, ui.x, a0i[2]);
            a1r[2] = fmaf(xv2, ur.y, a1r[2]);  a1i[2] = fmaf(xv2, ui.y, a1i[2]);
            a0r[3] = fmaf(xv3, ur.x, a0r[3]);  a0i[3] = fmaf(xv3, ui.x, a0i[3]);
            a1r[3] = fmaf(xv3, ur.y, a1r[3]);  a1i[3] = fmaf(xv3, ui.y, a1i[3]);
        }
    }

    float2* dst = (p == 0 ? g_QU : g_VU) + (size_t)h * NN * DIM + (size_t)tile * 64 * DIM;
    #pragma unroll
    for (int i = 0; i < 4; i++) {
        int row = rg * 4 + i;
        *(float4*)&dst[row * DIM + j0] = make_float4(a0r[i], a0i[i], a1r[i], a1i[i]);
    }
}

// ---------------------------------------------------------------------------
// Kernel 2: EUNN+modrelu recurrence — FROZEN R12 body (best measured).
// One warp per (h, n). Lane l owns complex elems 2l (A) and 2l+1 (B), state
// packed (re,im) for layer-1 only; everything downstream scalar.
//   tA = c1*A - s1*B ; nB = s1*A + c1*B          (packed f32x2, real coeffs)
//   zB = P*nB - Q*xd + in,   P = E*c2,  Q = E*s2*e1_{l+1},  E = e^{i(wB+phi2_l)}
//   zA = G'*tA + F*xu + in,  G' = e^{i wA}*c2p*e1,  F = e^{i wA}*s2p
//   xd = tA of lane l+1, xu = nB of lane l-1
//   modrelu: r = rsqrt(max(|z|^2,1e-10)) ~= 1/(|z|+1e-5);
//            sc = max(1 + (b-1e-5)*r, 0);  h = z*sc
// ---------------------------------------------------------------------------
__global__ void __launch_bounds__(128) k_recur(
    const float* __restrict__ bias,   // [4,64]
    const float* __restrict__ th1,    // [4,32]
    const float* __restrict__ ph1,    // [4,32]
    const float* __restrict__ th2,    // [4,31]
    const float* __restrict__ ph2,    // [4,31]
    const float* __restrict__ om)     // [4,64]
{
    const unsigned FULL = 0xffffffffu;
    int w = (blockIdx.x * blockDim.x + threadIdx.x) >> 5;   // 0..4095
    int l = threadIdx.x & 31;
    int h = w >> 10;
    int n = w & (NN - 1);
    int b = n >> 7;

    // layer-1 constants
    float c1, s1, e1r, e1i;
    sincosf(th1[h * 32 + l], &s1, &c1);
    sincosf(ph1[h * 32 + l], &e1i, &e1r);

    // layer-2 constants (pair l couples elems 2l+1, 2l+2)
    float c2 = 1.f, s2 = 0.f, p2 = 0.f;
    if (l < 31) {
        sincosf(th2[h * 31 + l], &s2, &c2);
        p2 = ph2[h * 31 + l];
    }
    float c2p = 1.f, s2p = 0.f;
    if (l > 0) sincosf(th2[h * 31 + l - 1], &s2p, &c2p);

    float omA = om[h * 64 + 2 * l];
    float omB = om[h * 64 + 2 * l + 1];

    // e1 of lane l+1 (lane 31: unused, s2=0 kills it)
    float e1nr = __shfl_down_sync(FULL, e1r, 1);
    float e1ni = __shfl_down_sync(FULL, e1i, 1);

    // E = e^{i(omB + phi2_l)}; P = E*c2; Q = E*s2*e1_next
    float Er, Ei;
    sincosf(omB + p2, &Ei, &Er);
    float Pr = c2 * Er, Pi = c2 * Ei;
    float Qr = s2 * (Er * e1nr - Ei * e1ni);
    float Qi = s2 * (Er * e1ni + Ei * e1nr);
    // G' = e^{i omA}*c2p*e1 ; F = e^{i omA}*s2p
    float cA_, sA_;
    sincosf(omA, &sA_, &cA_);
    float Gr = c2p * (cA_ * e1r - sA_ * e1i);
    float Gi = c2p * (cA_ * e1i + sA_ * e1r);
    float Fr = s2p * cA_, Fi = s2p * sA_;

    float bAp = bias[h * 64 + 2 * l]     - 1e-5f;
    float bBp = bias[h * 64 + 2 * l + 1] - 1e-5f;

    // packed real-coefficient constants for layer 1
    ull c1p  = pk(c1, c1);
    ull s1p  = pk(s1, s1);
    ull ns1p = pk(-s1, -s1);

    // per-warp constant input (QU, scalar) and per-step VU stream
    float4 qu = __ldg((const float4*)&g_QU[(h * NN + n) * DIM + 2 * l]);
    const float4* vup = (const float4*)&g_VU[((h * BB + b) * VV) * DIM + 2 * l];

    ull A2 = 0ull, B2 = 0ull;   // (re, im) packed state

    float4 vu = __ldg(vup); vup += DIM / 2;   // prefetch step 0

    #pragma unroll 4
    for (int v = 0; v < VV; v++) {
        float4 vun = __ldg(vup); vup += DIM / 2;   // prefetch next (pad covers v=127)

        // input term — scalar adds
        float inAr = qu.x + vu.x, inAi = qu.y + vu.y;
        float inBr = qu.z + vu.z, inBi = qu.w + vu.w;

        // layer 1 (packed, real coefficients)
        ull tA2 = fma2(c1p, A2, mul2(ns1p, B2));   // c1*A - s1*B  (re,im)
        ull nB2 = fma2(s1p, A2, mul2(c1p, B2));    // s1*A + c1*B  (re,im)

        // extract once, then shuffle scalars
        float tAr = lo32(tA2), tAi = hi32(tA2);
        float nBr = lo32(nB2), nBi = hi32(nB2);

        float xur = __shfl_up_sync(FULL, nBr, 1);     // nB of lane l-1
        float xui = __shfl_up_sync(FULL, nBi, 1);
        float xdr = __shfl_down_sync(FULL, tAr, 1);   // tA of lane l+1
        float xdi = __shfl_down_sync(FULL, tAi, 1);

        // B path: zB = P*nB - Q*xd + in   (complex, folded)
        float zBr = fmaf(Pr, nBr, fmaf(-Pi, nBi, fmaf(-Qr, xdr, fmaf( Qi, xdi, inBr))));
        float zBi = fmaf(Pr, nBi, fmaf( Pi, nBr, fmaf(-Qr, xdi, fmaf(-Qi, xdr, inBi))));

        // A path: zA = G'*tA + F*xu + in  (complex, folded)
        float zAr = fmaf(Gr, tAr, fmaf(-Gi, tAi, fmaf(Fr, xur, fmaf(-Fi, xui, inAr))));
        float zAi = fmaf(Gr, tAi, fmaf( Gi, tAr, fmaf(Fr, xui, fmaf( Fi, xur, inAi))));

        // modrelu — single MUFU per element; guard on the ALU pipe
        float sA = fmaf(zAi, zAi, zAr * zAr);
        float sB = fmaf(zBi, zBi, zBr * zBr);
        float rA = rsqrt_apx(fmaxf(sA, 1e-10f));
        float rB = rsqrt_apx(fmaxf(sB, 1e-10f));
        float scA = fmaxf(fmaf(bAp, rA, 1.0f), 0.0f);
        float scB = fmaxf(fmaf(bBp, rB, 1.0f), 0.0f);
        A2 = pk(zAr * scA, zAi * scA);
        B2 = pk(zBr * scB, zBi * scB);

        vu = vun;
    }

    float2* accp = (float2*)&g_acc[n * (HEADS * DIM) + h * DIM + 2 * l];
    *accp = make_float2(lo32(A2), lo32(B2));
}

// ---------------------------------------------------------------------------
// Kernel 3: y = acc @ W + b   ([1024,256] @ [256,64])
// 128 blocks x 256 threads; block handles 8 rows (better SM coverage than 64
// blocks). Warp-uniform ty -> a_s reads are broadcasts; W read as float2
// (256B contiguous per warp). Thread: row ty, cols 2tx, 2tx+1.
// ---------------------------------------------------------------------------
#define AST 264
__global__ void __launch_bounds__(256) k_proj(
    const float* __restrict__ W,    // [256,64]
    const float* __restrict__ bd,   // [64]
    float* __restrict__ out)        // [1024,64]
{
    __shared__ float a_s[8 * AST];
    int t = threadIdx.x;
    int row0 = blockIdx.x * 8;

    // stage 8 rows x 256 cols of g_acc = 512 float4
    const float4* g4 = (const float4*)(g_acc + row0 * 256);
    #pragma unroll
    for (int i = 0; i < 2; i++) {
        int g = t + 256 * i;            // float4 index; 64 float4 per row
        int r = g >> 6, c4 = g & 63;
        *(float4*)&a_s[r * AST + c4 * 4] = __ldg(g4 + g);
    }
    __syncthreads();

    int tx = t & 31, ty = t >> 5;       // ty warp-uniform (0..7)
    float2 s = __ldg((const float2*)(bd + 2 * tx));
    const float* arow = a_s + ty * AST;

    #pragma unroll 8
    for (int k = 0; k < 256; k++) {
        float a = arow[k];              // warp broadcast
        float2 wv = __ldg((const float2*)(W + k * 64 + 2 * tx));
        s.x = fmaf(a, wv.x, s.x);
        s.y = fmaf(a, wv.y, s.y);
    }
    *(float2*)(out + (row0 + ty) * 64 + 2 * tx) = s;
}

// ---------------------------------------------------------------------------
extern "C" void kernel_launch(void* const* d_in, const int* in_sizes, int n_in,
                              void* d_out, int out_size)
{
    const float* queries = (const float*)d_in[0];
    const float* values  = (const float*)d_in[1];
    const float* U_re    = (const float*)d_in[2];
    const float* U_im    = (const float*)d_in[3];
    const float* bias    = (const float*)d_in[4];
    const float* theta1  = (const float*)d_in[5];
    const float* phi1    = (const float*)d_in[6];
    const float* theta2  = (const float*)d_in[7];
    const float* phi2    = (const float*)d_in[8];
    const float* omega   = (const float*)d_in[9];
    const float* W_dense = (const float*)d_in[10];
    const float* b_dense = (const float*)d_in[11];
    float* out = (float*)d_out;

    k_compute_u<<<128, 512>>>(queries, values, U_re, U_im);
    k_recur<<<1024, 128>>>(bias, theta1, phi1, theta2, phi2, omega);
    k_proj<<<128, 256>>>(W_dense, b_dense, out);
}

// round 16
// speedup vs baseline: 1.5421x; 1.0072x over previous
#include <cuda_runtime.h>

#define HEADS 4
#define DIM   64
#define BB    8
#define QQ    128
#define VV    128
#define NN    (BB*QQ)   // 1024

typedef unsigned long long ull;

// Scratch (device globals — no allocation allowed). g_VU has one row of pad
// so the recurrence can prefetch one step past the end unconditionally.
__device__ float2 g_QU[HEADS * NN * DIM];                 // [h][n][j] complex
__device__ float2 g_VU[HEADS * BB * VV * DIM + DIM];      // [h][b][v][j] complex (+pad)
__device__ float  g_acc[NN * HEADS * DIM];                // [n][h*64+j] real

__device__ __forceinline__ float rsqrt_apx(float s) {
    float r; asm("rsqrt.approx.f32 %0,%1;" : "=f"(r) : "f"(s)); return r;
}
// f32x2 helpers (layer-1 only; real coefficients, no swaps)
__device__ __forceinline__ ull pk(float lo, float hi) {
    ull d; asm("mov.b64 %0,{%1,%2};" : "=l"(d) : "f"(lo), "f"(hi)); return d;
}
__device__ __forceinline__ float lo32(ull a) {
    float x; asm("{ .reg .b32 t; mov.b64 {%0,t},%1; }" : "=f"(x) : "l"(a)); return x;
}
__device__ __forceinline__ float hi32(ull a) {
    float x; asm("{ .reg .b32 t; mov.b64 {t,%0},%1; }" : "=f"(x) : "l"(a)); return x;
}
__device__ __forceinline__ ull fma2(ull a, ull b, ull c) {
    ull d; asm("fma.rn.f32x2 %0,%1,%2,%3;" : "=l"(d) : "l"(a), "l"(b), "l"(c)); return d;
}
__device__ __forceinline__ ull mul2(ull a, ull b) {
    ull d; asm("mul.rn.f32x2 %0,%1,%2;" : "=l"(d) : "l"(a), "l"(b)); return d;
}

// ---------------------------------------------------------------------------
// Kernel 1 (tiled GEMM): for part p (0:queries->g_QU, 1:values->g_VU), head h,
// 32-row tile:  out[row, j] = sum_k x[row,k] * U[h, p*64+k, j]  (complex)
// grid = 4 heads * 2 parts * 32 tiles = 256 blocks x 512 threads
// -> 2 blocks/SM = 8 warps/SMSP (was 4) to cover the 29-cyc LDS latency.
// smem 40KB/block (x 8KB + U 32KB); accumulators halve to 8 regs/thread.
// Thread t: j = 2*(t&31), 2*(t&31)+1; rows (t>>5)*2 .. +1. k blocked by 4.
// ---------------------------------------------------------------------------
__global__ void __launch_bounds__(512) k_compute_u(
    const float* __restrict__ q,      // [1024,64]
    const float* __restrict__ vals,   // [1024,64]
    const float* __restrict__ Ure,    // [4,128,64]
    const float* __restrict__ Uim)
{
    __shared__ float x_s[32 * 64];    // [r][k]
    __shared__ float ur_s[64 * 64];   // [k][j]
    __shared__ float ui_s[64 * 64];

    int t    = threadIdx.x;
    int tile = blockIdx.x & 31;
    int p    = (blockIdx.x >> 5) & 1;
    int h    = blockIdx.x >> 6;

    // stage x tile (32 rows x 64 cols) = 512 float4, conflict-free
    const float4* src4 = (const float4*)((p == 0 ? q : vals) + tile * 32 * 64);
    float4* xs4 = (float4*)x_s;
    xs4[t] = __ldg(src4 + t);

    // stage U tiles (64 k x 64 j, re and im) = 1024 float4 each
    const float4* ur4 = (const float4*)(Ure + h * 8192 + p * 4096);
    const float4* ui4 = (const float4*)(Uim + h * 8192 + p * 4096);
    float4* urs4 = (float4*)ur_s;
    float4* uis4 = (float4*)ui_s;
    #pragma unroll
    for (int i = 0; i < 2; i++) {
        urs4[t + 512 * i] = __ldg(ur4 + t + 512 * i);
        uis4[t + 512 * i] = __ldg(ui4 + t + 512 * i);
    }
    __syncthreads();

    int j0 = 2 * (t & 31);            // complex columns j0, j0+1
    int rg = t >> 5;                  // 0..15 -> rows rg*2, rg*2+1

    float a0r[2], a0i[2], a1r[2], a1i[2];
    #pragma unroll
    for (int i = 0; i < 2; i++) { a0r[i] = a0i[i] = a1r[i] = a1i[i] = 0.f; }

    #pragma unroll 4
    for (int k4 = 0; k4 < 64; k4 += 4) {
        // one LDS.128 per row (warp-uniform broadcast), 4 k's at a time
        float4 x0 = *(const float4*)&x_s[(rg * 2 + 0) * 64 + k4];
        float4 x1 = *(const float4*)&x_s[(rg * 2 + 1) * 64 + k4];
        const float* xp0 = (const float*)&x0;
        const float* xp1 = (const float*)&x1;
        #pragma unroll
        for (int kk = 0; kk < 4; kk++) {
            float2 ur = *(const float2*)&ur_s[(k4 + kk) * 64 + j0];
            float2 ui = *(const float2*)&ui_s[(k4 + kk) * 64 + j0];
            float xv0 = xp0[kk], xv1 = xp1[kk];
            a0r[0] = fmaf(xv0, ur.x, a0r[0]);  a0i[0] = fmaf(xv0, ui.x, a0i[0]);
            a1r[0] = fmaf(xv0, ur.y, a1r[0]);  a1i[0] = fmaf(xv0, ui.y, a1i[0]);
            a0r[1] = fmaf(xv1, ur.x, a0r[1]);  a0i[1] = fmaf(xv1, ui.x, a0i[1]);
            a1r[1] = fmaf(xv1, ur.y, a1r[1]);  a1i[1] = fmaf(xv1, ui.y, a1i[1]);
        }
    }

    float2* dst = (p == 0 ? g_QU : g_VU) + (size_t)h * NN * DIM + (size_t)tile * 32 * DIM;
    #pragma unroll
    for (int i = 0; i < 2; i++) {
        int row = rg * 2 + i;
        *(float4*)&dst[row * DIM + j0] = make_float4(a0r[i], a0i[i], a1r[i], a1i[i]);
    }
}

// ---------------------------------------------------------------------------
// Kernel 2: EUNN+modrelu recurrence — FROZEN R12 body (best measured).
// One warp per (h, n). Lane l owns complex elems 2l (A) and 2l+1 (B), state
// packed (re,im) for layer-1 only; everything downstream scalar.
//   tA = c1*A - s1*B ; nB = s1*A + c1*B          (packed f32x2, real coeffs)
//   zB = P*nB - Q*xd + in,   P = E*c2,  Q = E*s2*e1_{l+1},  E = e^{i(wB+phi2_l)}
//   zA = G'*tA + F*xu + in,  G' = e^{i wA}*c2p*e1,  F = e^{i wA}*s2p
//   xd = tA of lane l+1, xu = nB of lane l-1
//   modrelu: r = rsqrt(max(|z|^2,1e-10)) ~= 1/(|z|+1e-5);
//            sc = max(1 + (b-1e-5)*r, 0);  h = z*sc
// ---------------------------------------------------------------------------
__global__ void __launch_bounds__(128) k_recur(
    const float* __restrict__ bias,   // [4,64]
    const float* __restrict__ th1,    // [4,32]
    const float* __restrict__ ph1,    // [4,32]
    const float* __restrict__ th2,    // [4,31]
    const float* __restrict__ ph2,    // [4,31]
    const float* __restrict__ om)     // [4,64]
{
    const unsigned FULL = 0xffffffffu;
    int w = (blockIdx.x * blockDim.x + threadIdx.x) >> 5;   // 0..4095
    int l = threadIdx.x & 31;
    int h = w >> 10;
    int n = w & (NN - 1);
    int b = n >> 7;

    // layer-1 constants
    float c1, s1, e1r, e1i;
    sincosf(th1[h * 32 + l], &s1, &c1);
    sincosf(ph1[h * 32 + l], &e1i, &e1r);

    // layer-2 constants (pair l couples elems 2l+1, 2l+2)
    float c2 = 1.f, s2 = 0.f, p2 = 0.f;
    if (l < 31) {
        sincosf(th2[h * 31 + l], &s2, &c2);
        p2 = ph2[h * 31 + l];
    }
    float c2p = 1.f, s2p = 0.f;
    if (l > 0) sincosf(th2[h * 31 + l - 1], &s2p, &c2p);

    float omA = om[h * 64 + 2 * l];
    float omB = om[h * 64 + 2 * l + 1];

    // e1 of lane l+1 (lane 31: unused, s2=0 kills it)
    float e1nr = __shfl_down_sync(FULL, e1r, 1);
    float e1ni = __shfl_down_sync(FULL, e1i, 1);

    // E = e^{i(omB + phi2_l)}; P = E*c2; Q = E*s2*e1_next
    float Er, Ei;
    sincosf(omB + p2, &Ei, &Er);
    float Pr = c2 * Er, Pi = c2 * Ei;
    float Qr = s2 * (Er * e1nr - Ei * e1ni);
    float Qi = s2 * (Er * e1ni + Ei * e1nr);
    // G' = e^{i omA}*c2p*e1 ; F = e^{i omA}*s2p
    float cA_, sA_;
    sincosf(omA, &sA_, &cA_);
    float Gr = c2p * (cA_ * e1r - sA_ * e1i);
    float Gi = c2p * (cA_ * e1i + sA_ * e1r);
    float Fr = s2p * cA_, Fi = s2p * sA_;

    float bAp = bias[h * 64 + 2 * l]     - 1e-5f;
    float bBp = bias[h * 64 + 2 * l + 1] - 1e-5f;

    // packed real-coefficient constants for layer 1
    ull c1p  = pk(c1, c1);
    ull s1p  = pk(s1, s1);
    ull ns1p = pk(-s1, -s1);

    // per-warp constant input (QU, scalar) and per-step VU stream
    float4 qu = __ldg((const float4*)&g_QU[(h * NN + n) * DIM + 2 * l]);
    const float4* vup = (const float4*)&g_VU[((h * BB + b) * VV) * DIM + 2 * l];

    ull A2 = 0ull, B2 = 0ull;   // (re, im) packed state

    float4 vu = __ldg(vup); vup += DIM / 2;   // prefetch step 0

    #pragma unroll 4
    for (int v = 0; v < VV; v++) {
        float4 vun = __ldg(vup); vup += DIM / 2;   // prefetch next (pad covers v=127)

        // input term — scalar adds
        float inAr = qu.x + vu.x, inAi = qu.y + vu.y;
        float inBr = qu.z + vu.z, inBi = qu.w + vu.w;

        // layer 1 (packed, real coefficients)
        ull tA2 = fma2(c1p, A2, mul2(ns1p, B2));   // c1*A - s1*B  (re,im)
        ull nB2 = fma2(s1p, A2, mul2(c1p, B2));    // s1*A + c1*B  (re,im)

        // extract once, then shuffle scalars
        float tAr = lo32(tA2), tAi = hi32(tA2);
        float nBr = lo32(nB2), nBi = hi32(nB2);

        float xur = __shfl_up_sync(FULL, nBr, 1);     // nB of lane l-1
        float xui = __shfl_up_sync(FULL, nBi, 1);
        float xdr = __shfl_down_sync(FULL, tAr, 1);   // tA of lane l+1
        float xdi = __shfl_down_sync(FULL, tAi, 1);

        // B path: zB = P*nB - Q*xd + in   (complex, folded)
        float zBr = fmaf(Pr, nBr, fmaf(-Pi, nBi, fmaf(-Qr, xdr, fmaf( Qi, xdi, inBr))));
        float zBi = fmaf(Pr, nBi, fmaf( Pi, nBr, fmaf(-Qr, xdi, fmaf(-Qi, xdr, inBi))));

        // A path: zA = G'*tA + F*xu + in  (complex, folded)
        float zAr = fmaf(Gr, tAr, fmaf(-Gi, tAi, fmaf(Fr, xur, fmaf(-Fi, xui, inAr))));
        float zAi = fmaf(Gr, tAi, fmaf( Gi, tAr, fmaf(Fr, xui, fmaf( Fi, xur, inAi))));

        // modrelu — single MUFU per element; guard on the ALU pipe
        float sA = fmaf(zAi, zAi, zAr * zAr);
        float sB = fmaf(zBi, zBi, zBr * zBr);
        float rA = rsqrt_apx(fmaxf(sA, 1e-10f));
        float rB = rsqrt_apx(fmaxf(sB, 1e-10f));
        float scA = fmaxf(fmaf(bAp, rA, 1.0f), 0.0f);
        float scB = fmaxf(fmaf(bBp, rB, 1.0f), 0.0f);
        A2 = pk(zAr * scA, zAi * scA);
        B2 = pk(zBr * scB, zBi * scB);

        vu = vun;
    }

    float2* accp = (float2*)&g_acc[n * (HEADS * DIM) + h * DIM + 2 * l];
    *accp = make_float2(lo32(A2), lo32(B2));
}

// ---------------------------------------------------------------------------
// Kernel 3: y = acc @ W + b   ([1024,256] @ [256,64])
// 128 blocks x 256 threads; block handles 8 rows. Warp-uniform ty -> a_s
// reads are broadcasts; W read as float2 (256B contiguous per warp).
// ---------------------------------------------------------------------------
#define AST 264
__global__ void __launch_bounds__(256) k_proj(
    const float* __restrict__ W,    // [256,64]
    const float* __restrict__ bd,   // [64]
    float* __restrict__ out)        // [1024,64]
{
    __shared__ float a_s[8 * AST];
    int t = threadIdx.x;
    int row0 = blockIdx.x * 8;

    // stage 8 rows x 256 cols of g_acc = 512 float4
    const float4* g4 = (const float4*)(g_acc + row0 * 256);
    #pragma unroll
    for (int i = 0; i < 2; i++) {
        int g = t + 256 * i;            // float4 index; 64 float4 per row
        int r = g >> 6, c4 = g & 63;
        *(float4*)&a_s[r * AST + c4 * 4] = __ldg(g4 + g);
    }
    __syncthreads();

    int tx = t & 31, ty = t >> 5;       // ty warp-uniform (0..7)
    float2 s = __ldg((const float2*)(bd + 2 * tx));
    const float* arow = a_s + ty * AST;

    #pragma unroll 8
    for (int k = 0; k < 256; k++) {
        float a = arow[k];              // warp broadcast
        float2 wv = __ldg((const float2*)(W + k * 64 + 2 * tx));
        s.x = fmaf(a, wv.x, s.x);
        s.y = fmaf(a, wv.y, s.y);
    }
    *(float2*)(out + (row0 + ty) * 64 + 2 * tx) = s;
}

// ---------------------------------------------------------------------------
extern "C" void kernel_launch(void* const* d_in, const int* in_sizes, int n_in,
                              void* d_out, int out_size)
{
    const float* queries = (const float*)d_in[0];
    const float* values  = (const float*)d_in[1];
    const float* U_re    = (const float*)d_in[2];
    const float* U_im    = (const float*)d_in[3];
    const float* bias    = (const float*)d_in[4];
    const float* theta1  = (const float*)d_in[5];
    const float* phi1    = (const float*)d_in[6];
    const float* theta2  = (const float*)d_in[7];
    const float* phi2    = (const float*)d_in[8];
    const float* omega   = (const float*)d_in[9];
    const float* W_dense = (const float*)d_in[10];
    const float* b_dense = (const float*)d_in[11];
    float* out = (float*)d_out;

    k_compute_u<<<256, 512>>>(queries, values, U_re, U_im);
    k_recur<<<1024, 128>>>(bias, theta1, phi1, theta2, phi2, omega);
    k_proj<<<128, 256>>>(W_dense, b_dense, out);
}